// round 16
// baseline (speedup 1.0000x reference)
#include <cuda_runtime.h>
#include <cuda_fp16.h>
#include <math.h>
#include <stdint.h>

#define Bb 32
#define Nn 1024
#define Cc 768
#define Mm 64
#define Hh 12
#define Dd 64

// ---------------- scratch (__device__ globals per allocation contract) ------
__device__ float g_ss [Bb * Mm];           // per-z-row sum of squares
__device__ float g_bkv[2 * Cc];            // [bk | bv]
__device__ float g_bqc[896];               // [bq | bc | 0]

__device__ __half g_cth[Bb * Nn * Mm];     // cluster weights fp16 (n-major)
__device__ __half g_xh [Bb * Nn * Cc];     // x  fp16
__device__ __half g_qh [Bb * Nn * Cc];     // q  fp16
__device__ __half g_kvh[Bb * Mm * 2 * Cc]; // K|V fp16
__device__ __half g_oh [Bb * Nn * Cc];     // attn out fp16
__device__ __half g_zh [Bb * Mm * Cc];     // z fp16 (pre-normalization)
__device__ __half g_wqc [896 * Cc];        // [Wq | Wc | 0]  fp16
__device__ __half g_wkvp[3 * Cc * Cc];     // [Wk | Wv | Wp] fp16

// ---------------- helpers ---------------------------------------------------
__device__ __forceinline__ uint32_t smem_u32(const void* p) {
    uint32_t a;
    asm("{ .reg .u64 t; cvta.to.shared.u64 t, %1; cvt.u32.u64 %0, t; }"
        : "=r"(a) : "l"(p));
    return a;
}
#define CP16(saddr, gaddr) \
    asm volatile("cp.async.cg.shared.global [%0], [%1], 16;" \
                 :: "r"(saddr), "l"(gaddr))
#define CP_COMMIT() asm volatile("cp.async.commit_group;")
#define CP_WAIT(n)  asm volatile("cp.async.wait_group %0;" :: "n"(n))

#define LDSM4(r, a) \
    asm volatile("ldmatrix.sync.aligned.m8n8.x4.shared.b16 {%0,%1,%2,%3}, [%4];" \
        : "=r"((r)[0]), "=r"((r)[1]), "=r"((r)[2]), "=r"((r)[3]) : "r"(a))
#define LDSM4T(r, a) \
    asm volatile("ldmatrix.sync.aligned.m8n8.x4.trans.shared.b16 {%0,%1,%2,%3}, [%4];" \
        : "=r"((r)[0]), "=r"((r)[1]), "=r"((r)[2]), "=r"((r)[3]) : "r"(a))

#define MMA_F16(c, a, b0, b1) \
    asm volatile("mma.sync.aligned.m16n8k16.row.col.f32.f16.f16.f32 " \
        "{%0,%1,%2,%3},{%4,%5,%6,%7},{%8,%9},{%0,%1,%2,%3};" \
        : "+f"((c)[0]), "+f"((c)[1]), "+f"((c)[2]), "+f"((c)[3]) \
        : "r"((a)[0]), "r"((a)[1]), "r"((a)[2]), "r"((a)[3]), "r"(b0), "r"(b1))

__device__ __forceinline__ uint2 cvt4(float4 a) {
    __half2 h0 = __floats2half2_rn(a.x, a.y);
    __half2 h1 = __floats2half2_rn(a.z, a.w);
    return make_uint2(*(uint32_t*)&h0, *(uint32_t*)&h1);
}

// ---------------- one-shot converter: x, weights, biases, ss zero ------------
__global__ __launch_bounds__(256) void cvt_all(
    const float4* __restrict__ x,
    const float4* __restrict__ wq, const float4* __restrict__ wk,
    const float4* __restrict__ wv, const float4* __restrict__ wp,
    const float4* __restrict__ wc,
    const float4* __restrict__ bq, const float4* __restrict__ bc,
    const float4* __restrict__ bk, const float4* __restrict__ bv)
{
    constexpr size_t N4X = (size_t)Bb * Nn * Cc / 4;
    constexpr size_t W4  = (size_t)Cc * Cc / 4;
    constexpr size_t WC4 = (size_t)Mm * Cc / 4;
    constexpr size_t O0 = N4X;
    constexpr size_t O1 = O0 + W4;
    constexpr size_t O2 = O1 + W4;
    constexpr size_t O3 = O2 + W4;
    constexpr size_t O4 = O3 + W4;
    constexpr size_t O5 = O4 + WC4;
    constexpr size_t O6 = O5 + WC4;
    constexpr size_t O7 = O6 + 192;
    constexpr size_t O8 = O7 + 16;
    constexpr size_t O9 = O8 + 16;
    constexpr size_t OA = O9 + 192;
    constexpr size_t OB = OA + 192;
    constexpr size_t OC = OB + Bb * Mm / 4;   // zero g_ss (512 float4)

    size_t i = (size_t)blockIdx.x * 256 + threadIdx.x;
    if (i < O0) {
        ((uint2*)g_xh)[i] = cvt4(x[i]);
    } else if (i < O1) {
        size_t j = i - O0; ((uint2*)g_wqc)[j] = cvt4(wq[j]);
    } else if (i < O2) {
        size_t j = i - O1; ((uint2*)g_wkvp)[j] = cvt4(wk[j]);
    } else if (i < O3) {
        size_t j = i - O2; ((uint2*)(g_wkvp + (size_t)Cc * Cc))[j] = cvt4(wv[j]);
    } else if (i < O4) {
        size_t j = i - O3; ((uint2*)(g_wkvp + (size_t)2 * Cc * Cc))[j] = cvt4(wp[j]);
    } else if (i < O5) {
        size_t j = i - O4; ((uint2*)(g_wqc + (size_t)768 * Cc))[j] = cvt4(wc[j]);
    } else if (i < O6) {
        size_t j = i - O5; ((uint2*)(g_wqc + (size_t)832 * Cc))[j] = make_uint2(0, 0);
    } else if (i < O7) {
        size_t j = i - O6; ((float4*)g_bqc)[j] = bq[j];
    } else if (i < O8) {
        size_t j = i - O7; ((float4*)(g_bqc + 768))[j] = bc[j];
    } else if (i < O9) {
        size_t j = i - O8;
        ((float4*)(g_bqc + 832))[j] = make_float4(0.f, 0.f, 0.f, 0.f);
    } else if (i < OA) {
        size_t j = i - O9; ((float4*)g_bkv)[j] = bk[j];
    } else if (i < OB) {
        size_t j = i - OA; ((float4*)(g_bkv + Cc))[j] = bv[j];
    } else if (i < OC) {
        size_t j = i - OB;
        ((float4*)g_ss)[j] = make_float4(0.f, 0.f, 0.f, 0.f);
    }
}

// ---------------- fp16 GEMM NT via mma.sync (3-stage pipeline) ---------------
// C(I,J) = A(I,768)·B(J,768)^T + bias.
// MODE 0: plain. MODE 2: fused Q+cluster epilogue. MODE 3: per-A-row L2 scale
// (reads rss; v = acc/max(sqrt(ss),1e-12) + bias) for the KV projection.
template <int TN, int MODE, bool OUTH>
__global__ __launch_bounds__(256) void gemm_tc(
    const __half* __restrict__ Ah, const __half* __restrict__ Bh,
    const float* __restrict__ rss,
    const float* __restrict__ bias, void* __restrict__ CoutV, int J)
{
    constexpr int K = Cc;
    constexpr int KC = 32;
    constexpr int NCH = K / KC;        // 24
    constexpr int ABY = 128 * 64;      // 8 KB
    constexpr int BBY = TN * 64;
    constexpr int STAGE = ABY + BBY;
    constexpr int TNW = TN / 4;
    constexpr int NT = TNW / 8;
    constexpr int NP = NT / 2;

    extern __shared__ char smem[];
    const uint32_t s0 = smem_u32(smem);
    const uint32_t sb[3] = {s0, s0 + STAGE, s0 + 2 * STAGE};

    const int tid = threadIdx.x;
    const int wid = tid >> 5;
    const int lane = tid & 31;
    const int wm = wid & 1;
    const int wn = wid >> 1;
    const int i0 = blockIdx.y * 128;
    const int j0 = blockIdx.x * TN;

    float acc[4][NT][4];
#pragma unroll
    for (int a = 0; a < 4; a++)
#pragma unroll
        for (int b = 0; b < NT; b++)
#pragma unroll
            for (int c = 0; c < 4; c++) acc[a][b][c] = 0.f;

    auto prefetch = [&](int ch, int s) {
        const uint32_t base = sb[s];
        const int k0 = ch * KC;
#pragma unroll
        for (int it = 0; it < 2; it++) {
            int id = tid + it * 256;
            int row = id >> 2, c = id & 3;
            uint32_t off = row * 64 + (((c ^ (row >> 1)) & 3) << 4);
            CP16(base + off, Ah + (size_t)(i0 + row) * K + k0 + c * 8);
        }
#pragma unroll
        for (int it = 0; it < (TN * 4) / 256; it++) {
            int id = tid + it * 256;
            int row = id >> 2, c = id & 3;
            uint32_t off = row * 64 + (((c ^ (row >> 1)) & 3) << 4);
            CP16(base + ABY + off, Bh + (size_t)(j0 + row) * K + k0 + c * 8);
        }
    };

    auto compute = [&](int s) {
        const uint32_t ab = sb[s];
        const uint32_t bhb = ab + ABY;
#pragma unroll
        for (int ks = 0; ks < 2; ks++) {
            uint32_t BH[NP][4];
#pragma unroll
            for (int p = 0; p < NP; p++) {
                int row = wn * TNW + p * 16 + (lane & 15);
                int ch = ks * 2 + (lane >> 4);
                uint32_t off = row * 64 + (((ch ^ (row >> 1)) & 3) << 4);
                LDSM4(BH[p], bhb + off);
            }
#pragma unroll
            for (int mt = 0; mt < 4; mt++) {
                int row = wm * 64 + mt * 16 + (lane & 15);
                int ch = ks * 2 + (lane >> 4);
                uint32_t off = row * 64 + (((ch ^ (row >> 1)) & 3) << 4);
                uint32_t AH[4];
                LDSM4(AH, ab + off);
#pragma unroll
                for (int nt = 0; nt < NT; nt++)
                    MMA_F16(acc[mt][nt], AH,
                            BH[nt >> 1][nt & 1], BH[nt >> 1][(nt & 1) + 2]);
            }
        }
    };

    prefetch(0, 0); CP_COMMIT();
    prefetch(1, 1); CP_COMMIT();
    for (int ch = 0; ch < NCH; ch++) {
        CP_WAIT(1);
        __syncthreads();
        compute(ch % 3);
        if (ch + 2 < NCH) prefetch(ch + 2, (ch + 2) % 3);
        CP_COMMIT();
    }

#pragma unroll
    for (int mt = 0; mt < 4; mt++) {
        const int gr = i0 + wm * 64 + mt * 16 + (lane >> 2);
        float inv0 = 1.f, inv1 = 1.f;
        if constexpr (MODE == 3) {
            inv0 = 1.f / fmaxf(sqrtf(__ldg(rss + gr)), 1e-12f);
            inv1 = 1.f / fmaxf(sqrtf(__ldg(rss + gr + 8)), 1e-12f);
        }
#pragma unroll
        for (int nt = 0; nt < NT; nt++) {
            const int gc = j0 + wn * TNW + nt * 8 + (lane & 3) * 2;
            const float b0 = __ldg(bias + gc), b1 = __ldg(bias + gc + 1);
            float v0, v1, v2, v3;
            if constexpr (MODE == 3) {
                v0 = acc[mt][nt][0] * inv0 + b0;
                v1 = acc[mt][nt][1] * inv0 + b1;
                v2 = acc[mt][nt][2] * inv1 + b0;
                v3 = acc[mt][nt][3] * inv1 + b1;
            } else {
                v0 = acc[mt][nt][0] + b0; v1 = acc[mt][nt][1] + b1;
                v2 = acc[mt][nt][2] + b0; v3 = acc[mt][nt][3] + b1;
            }
            if constexpr (MODE == 2) {
                if (gc < Cc) {
                    __half2 h0 = __floats2half2_rn(v0, v1);
                    __half2 h1 = __floats2half2_rn(v2, v3);
                    *(__half2*)(g_qh + (size_t)gr * Cc + gc) = h0;
                    *(__half2*)(g_qh + (size_t)(gr + 8) * Cc + gc) = h1;
                } else {
                    const int gcl = gc - Cc;
                    if (gcl < Mm) {
                        v0 = 1.f / (1.f + __expf(-v0)) * (1.f / Nn);
                        v1 = 1.f / (1.f + __expf(-v1)) * (1.f / Nn);
                        v2 = 1.f / (1.f + __expf(-v2)) * (1.f / Nn);
                        v3 = 1.f / (1.f + __expf(-v3)) * (1.f / Nn);
                        __half2 h0 = __floats2half2_rn(v0, v1);
                        __half2 h1 = __floats2half2_rn(v2, v3);
                        *(__half2*)(g_cth + (size_t)gr * Mm + gcl) = h0;
                        *(__half2*)(g_cth + (size_t)(gr + 8) * Mm + gcl) = h1;
                    }
                }
            } else if constexpr (OUTH) {
                __half* Ch = (__half*)CoutV;
                __half2 h0 = __floats2half2_rn(v0, v1);
                __half2 h1 = __floats2half2_rn(v2, v3);
                *(__half2*)(Ch + (size_t)gr * J + gc) = h0;
                *(__half2*)(Ch + (size_t)(gr + 8) * J + gc) = h1;
            } else {
                float* Cf = (float*)CoutV;
                *(float2*)(Cf + (size_t)gr * J + gc) = make_float2(v0, v1);
                *(float2*)(Cf + (size_t)(gr + 8) * J + gc) = make_float2(v2, v3);
            }
        }
    }
}

// ---------------- tensor-core z = ct^T @ x: fp16 z + row sumsq atomics -------
__global__ __launch_bounds__(256) void gemm_ctz(
    const __half* __restrict__ ct, const __half* __restrict__ xh,
    __half* __restrict__ zh, float* __restrict__ ss)
{
    constexpr int KC = 32;
    constexpr int NCH = Nn / KC;     // 32
    constexpr int CTBY = 32 * 128;   // 4 KB
    constexpr int XBY  = 32 * 256;   // 8 KB
    constexpr int STAGE = CTBY + XBY;

    __shared__ __align__(128) char smem[3 * STAGE];   // 36 KB
    const uint32_t s0 = smem_u32(smem);

    const int b = blockIdx.z;
    const int j0 = blockIdx.x * 128;
    const int tid = threadIdx.x;
    const int wid = tid >> 5, lane = tid & 31;
    const int m0 = (wid & 3) * 16;
    const int jw = (wid >> 2) * 64;

    float o[8][4];
#pragma unroll
    for (int t = 0; t < 8; t++)
#pragma unroll
        for (int c = 0; c < 4; c++) o[t][c] = 0.f;

    auto prefetch = [&](int chn, int s) {
        const uint32_t base = s0 + s * STAGE;
        const int k0 = chn * KC;
        {
            int r = tid >> 3, c = tid & 7;
            uint32_t off = r * 128 + (((c ^ (r & 7)) & 7) << 4);
            CP16(base + off, ct + ((size_t)b * Nn + k0 + r) * Mm + c * 8);
        }
#pragma unroll
        for (int it = 0; it < 2; it++) {
            int id = tid + it * 256;
            int r = id >> 4, c = id & 15;
            uint32_t off = r * 256 + (((c ^ (r & 7)) & 15) << 4);
            CP16(base + CTBY + off,
                 xh + ((size_t)b * Nn + k0 + r) * Cc + j0 + c * 8);
        }
    };

    auto compute = [&](int s) {
        const uint32_t cb = s0 + s * STAGE, xb = cb + CTBY;
#pragma unroll
        for (int ks = 0; ks < 2; ks++) {
            const int row = ks * 16 + (lane & 7) + ((lane >> 4) & 1) * 8;
            uint32_t A[4];
            {
                int c = (m0 >> 3) + ((lane >> 3) & 1);
                LDSM4T(A, cb + row * 128 + (((c ^ (row & 7)) & 7) << 4));
            }
#pragma unroll
            for (int jt = 0; jt < 4; jt++) {
                uint32_t Bf[4];
                int c = ((jw + jt * 16) >> 3) + ((lane >> 3) & 1);
                LDSM4T(Bf, xb + row * 256 + (((c ^ (row & 7)) & 15) << 4));
                MMA_F16(o[jt * 2],     A, Bf[0], Bf[2]);
                MMA_F16(o[jt * 2 + 1], A, Bf[1], Bf[3]);
            }
        }
    };

    prefetch(0, 0); CP_COMMIT();
    prefetch(1, 1); CP_COMMIT();
    for (int ch = 0; ch < NCH; ch++) {
        CP_WAIT(1);
        __syncthreads();
        compute(ch % 3);
        if (ch + 2 < NCH) prefetch(ch + 2, (ch + 2) % 3);
        CP_COMMIT();
    }

    const int r0 = m0 + (lane >> 2);
    float s0acc = 0.f, s1acc = 0.f;
#pragma unroll
    for (int t = 0; t < 8; t++) {
        const int col = j0 + jw + t * 8 + (lane & 3) * 2;
        __half* zp = zh + ((size_t)b * Mm + r0) * Cc + col;
        __half2 h0 = __floats2half2_rn(o[t][0], o[t][1]);
        __half2 h1 = __floats2half2_rn(o[t][2], o[t][3]);
        *(__half2*)zp = h0;
        *(__half2*)(zp + 8 * Cc) = h1;
        s0acc += o[t][0] * o[t][0] + o[t][1] * o[t][1];
        s1acc += o[t][2] * o[t][2] + o[t][3] * o[t][3];
    }
    atomicAdd(ss + b * Mm + r0, s0acc);
    atomicAdd(ss + b * Mm + r0 + 8, s1acc);
}

// ---------------- tensor-core attention --------------------------------------
__global__ __launch_bounds__(256) void attn_tc(
    const __half* __restrict__ qh, const __half* __restrict__ kvh,
    __half* __restrict__ oh)
{
    const int bh = blockIdx.x;
    const int b = bh / Hh;
    const int h = bh % Hh;
    const int n0 = blockIdx.y * 128;

    __shared__ __align__(128) char smem[32768];
    const uint32_t sq = smem_u32(smem);
    const uint32_t sk = sq + 16384;
    const uint32_t sv = sk + 8192;

    const int tid = threadIdx.x;
    const int wid = tid >> 5;
    const int lane = tid & 31;

#pragma unroll
    for (int it = 0; it < 4; it++) {
        int id = tid + it * 256;
        int row = id >> 3, c = id & 7;
        uint32_t off = row * 128 + (((c ^ row) & 7) << 4);
        CP16(sq + off, qh + (size_t)(b * Nn + n0 + row) * Cc + h * Dd + c * 8);
    }
#pragma unroll
    for (int it = 0; it < 2; it++) {
        int id = tid + it * 256;
        int row = id >> 3, c = id & 7;
        uint32_t off = row * 128 + (((c ^ row) & 7) << 4);
        const size_t base = (size_t)(b * Mm + row) * (2 * Cc) + h * Dd + c * 8;
        CP16(sk + off, kvh + base);
        CP16(sv + off, kvh + base + Cc);
    }
    CP_COMMIT();
    CP_WAIT(0);
    __syncthreads();

    float s[8][4];
#pragma unroll
    for (int t = 0; t < 8; t++)
#pragma unroll
        for (int c = 0; c < 4; c++) s[t][c] = 0.f;

#pragma unroll
    for (int kf = 0; kf < 4; kf++) {
        const int ch = kf * 2 + (lane >> 4);
        uint32_t A[4];
        {
            int row = wid * 16 + (lane & 15);
            LDSM4(A, sq + row * 128 + (((ch ^ row) & 7) << 4));
        }
        uint32_t Bk[4][4];
#pragma unroll
        for (int p = 0; p < 4; p++) {
            int row = p * 16 + (lane & 15);
            LDSM4(Bk[p], sk + row * 128 + (((ch ^ row) & 7) << 4));
        }
#pragma unroll
        for (int nt = 0; nt < 8; nt++)
            MMA_F16(s[nt], A, Bk[nt >> 1][nt & 1], Bk[nt >> 1][(nt & 1) + 2]);
    }

    const float scale = 0.125f;
    float m0 = -1e30f, m1 = -1e30f;
#pragma unroll
    for (int t = 0; t < 8; t++) {
#pragma unroll
        for (int c = 0; c < 4; c++) s[t][c] *= scale;
        m0 = fmaxf(m0, fmaxf(s[t][0], s[t][1]));
        m1 = fmaxf(m1, fmaxf(s[t][2], s[t][3]));
    }
    m0 = fmaxf(m0, __shfl_xor_sync(0xffffffff, m0, 1));
    m0 = fmaxf(m0, __shfl_xor_sync(0xffffffff, m0, 2));
    m1 = fmaxf(m1, __shfl_xor_sync(0xffffffff, m1, 1));
    m1 = fmaxf(m1, __shfl_xor_sync(0xffffffff, m1, 2));

    float l0 = 0.f, l1 = 0.f;
    uint32_t P[4][4];
#pragma unroll
    for (int t = 0; t < 8; t++) {
        float p0 = __expf(s[t][0] - m0);
        float p1 = __expf(s[t][1] - m0);
        float p2 = __expf(s[t][2] - m1);
        float p3 = __expf(s[t][3] - m1);
        l0 += p0 + p1;
        l1 += p2 + p3;
        __half2 h01 = __floats2half2_rn(p0, p1);
        __half2 h23 = __floats2half2_rn(p2, p3);
        P[t >> 1][(t & 1) * 2 + 0] = *(uint32_t*)&h01;
        P[t >> 1][(t & 1) * 2 + 1] = *(uint32_t*)&h23;
    }
    l0 += __shfl_xor_sync(0xffffffff, l0, 1);
    l0 += __shfl_xor_sync(0xffffffff, l0, 2);
    l1 += __shfl_xor_sync(0xffffffff, l1, 1);
    l1 += __shfl_xor_sync(0xffffffff, l1, 2);

    float o[8][4];
#pragma unroll
    for (int t = 0; t < 8; t++)
#pragma unroll
        for (int c = 0; c < 4; c++) o[t][c] = 0.f;

#pragma unroll
    for (int kf = 0; kf < 4; kf++) {
#pragma unroll
        for (int dt = 0; dt < 4; dt++) {
            uint32_t VF[4];
            int row = kf * 16 + (lane & 15);
            int ch = dt * 2 + (lane >> 4);
            LDSM4T(VF, sv + row * 128 + (((ch ^ row) & 7) << 4));
            MMA_F16(o[dt * 2],     P[kf], VF[0], VF[1]);
            MMA_F16(o[dt * 2 + 1], P[kf], VF[2], VF[3]);
        }
    }

    const float inv0 = 1.f / l0, inv1 = 1.f / l1;
    const int r = wid * 16 + (lane >> 2);
    const size_t ob = (size_t)(b * Nn + n0 + r) * Cc + h * Dd;
#pragma unroll
    for (int t = 0; t < 8; t++) {
        const int col = t * 8 + (lane & 3) * 2;
        __half2 h0 = __floats2half2_rn(o[t][0] * inv0, o[t][1] * inv0);
        __half2 h1 = __floats2half2_rn(o[t][2] * inv1, o[t][3] * inv1);
        *(__half2*)(oh + ob + col) = h0;
        *(__half2*)(oh + ob + 8 * Cc + col) = h1;
    }
}

// ---------------------------------------------------------------------------
extern "C" void kernel_launch(void* const* d_in, const int* in_sizes, int n_in,
                              void* d_out, int out_size)
{
    (void)in_sizes; (void)n_in; (void)out_size;
    const float* x  = (const float*)d_in[0];
    const float* Wc = (const float*)d_in[1];
    const float* bc = (const float*)d_in[2];
    const float* Wq = (const float*)d_in[3];
    const float* bq = (const float*)d_in[4];
    const float* Wk = (const float*)d_in[5];
    const float* bk = (const float*)d_in[6];
    const float* Wv = (const float*)d_in[7];
    const float* bv = (const float*)d_in[8];
    const float* Wp = (const float*)d_in[9];
    const float* bp = (const float*)d_in[10];
    float* out = (float*)d_out;

    float *ss, *bkv, *bqc;
    __half *cth, *xh, *qh, *kvh, *oh, *zh, *wqc, *wkvp;
    cudaGetSymbolAddress((void**)&ss,   g_ss);
    cudaGetSymbolAddress((void**)&bkv,  g_bkv);
    cudaGetSymbolAddress((void**)&bqc,  g_bqc);
    cudaGetSymbolAddress((void**)&cth,  g_cth);
    cudaGetSymbolAddress((void**)&xh,   g_xh);
    cudaGetSymbolAddress((void**)&qh,   g_qh);
    cudaGetSymbolAddress((void**)&kvh,  g_kvh);
    cudaGetSymbolAddress((void**)&oh,   g_oh);
    cudaGetSymbolAddress((void**)&zh,   g_zh);
    cudaGetSymbolAddress((void**)&wqc,  g_wqc);
    cudaGetSymbolAddress((void**)&wkvp, g_wkvp);

    constexpr int SMEM3 = 3 * (128 * 64 + 128 * 64);   // 48 KB (3-stage)
    cudaFuncSetAttribute(gemm_tc<128, 0, false>,
        cudaFuncAttributeMaxDynamicSharedMemorySize, SMEM3);
    cudaFuncSetAttribute(gemm_tc<128, 0, true>,
        cudaFuncAttributeMaxDynamicSharedMemorySize, SMEM3);
    cudaFuncSetAttribute(gemm_tc<128, 2, true>,
        cudaFuncAttributeMaxDynamicSharedMemorySize, SMEM3);
    cudaFuncSetAttribute(gemm_tc<128, 3, true>,
        cudaFuncAttributeMaxDynamicSharedMemorySize, SMEM3);

    const int IN = Bb * Nn;   // 32768
    const int IM = Bb * Mm;   // 2048

    // 1. one-shot convert (x, weights, biases) + g_ss zeroing
    {
        constexpr size_t TOT = (size_t)Bb * Nn * Cc / 4 + 4 * (Cc * Cc / 4)
                             + 2 * (Mm * Cc / 4) + 192 + 16 + 16 + 192 + 192
                             + Bb * Mm / 4;
        cvt_all<<<(unsigned)((TOT + 255) / 256), 256>>>(
            (const float4*)x, (const float4*)Wq, (const float4*)Wk,
            (const float4*)Wv, (const float4*)Wp, (const float4*)Wc,
            (const float4*)bq, (const float4*)bc,
            (const float4*)bk, (const float4*)bv);
    }

    // 2. fused Q + cluster logits: [q | ct] = x @ [Wq|Wc|0]^T + [bq|bc|0]
    gemm_tc<128, 2, true><<<dim3(7, IN / 128), 256, SMEM3>>>(
        xh, wqc, nullptr, bqc, nullptr, 896);

    // 3. z[b] = ct[b]^T @ x[b] -> fp16 zh + per-row sumsq atomics
    gemm_ctz<<<dim3(Cc / 128, 1, Bb), 256>>>(cth, xh, zh, ss);

    // 4. KV = norm(z) @ [Wk|Wv]^T + [bk|bv] -> fp16 (L2 scale in epilogue)
    gemm_tc<128, 3, true><<<dim3(2 * Cc / 128, IM / 128), 256, SMEM3>>>(
        zh, wkvp, ss, bkv, kvh, 2 * Cc);

    // 5. tensor-core attention -> o (fp16)
    attn_tc<<<dim3(Bb * Hh, Nn / 128), 256>>>(qh, kvh, oh);

    // 6. out = o @ Wp^T + bp (fp32 out)
    gemm_tc<128, 0, false><<<dim3(Cc / 128, IN / 128), 256, SMEM3>>>(
        oh, wkvp + (size_t)2 * Cc * Cc, nullptr, bp, out, Cc);
}

// round 17
// speedup vs baseline: 1.0433x; 1.0433x over previous
#include <cuda_runtime.h>
#include <cuda_fp16.h>
#include <math.h>
#include <stdint.h>

#define Bb 32
#define Nn 1024
#define Cc 768
#define Mm 64
#define Hh 12
#define Dd 64

// ---------------- scratch (__device__ globals per allocation contract) ------
__device__ float g_ss [Bb * Mm];           // per-z-row sum of squares
__device__ float g_bkv[2 * Cc];            // [bk | bv]
__device__ float g_bqc[896];               // [bq | bc | 0]

__device__ __half g_cth[Bb * Nn * Mm];     // cluster weights fp16 (n-major)
__device__ __half g_xh [Bb * Nn * Cc];     // x  fp16
__device__ __half g_qh [Bb * Nn * Cc];     // q  fp16
__device__ __half g_kvh[Bb * Mm * 2 * Cc]; // K|V fp16
__device__ __half g_oh [Bb * Nn * Cc];     // attn out fp16
__device__ __half g_zh [Bb * Mm * Cc];     // z fp16 (pre-normalization)
__device__ __half g_wqc [896 * Cc];        // [Wq | Wc | 0]  fp16
__device__ __half g_wkvp[3 * Cc * Cc];     // [Wk | Wv | Wp] fp16

// ---------------- helpers ---------------------------------------------------
__device__ __forceinline__ uint32_t smem_u32(const void* p) {
    uint32_t a;
    asm("{ .reg .u64 t; cvta.to.shared.u64 t, %1; cvt.u32.u64 %0, t; }"
        : "=r"(a) : "l"(p));
    return a;
}
#define CP16(saddr, gaddr) \
    asm volatile("cp.async.cg.shared.global [%0], [%1], 16;" \
                 :: "r"(saddr), "l"(gaddr))
#define CP_COMMIT() asm volatile("cp.async.commit_group;")
#define CP_WAIT(n)  asm volatile("cp.async.wait_group %0;" :: "n"(n))

#define LDSM4(r, a) \
    asm volatile("ldmatrix.sync.aligned.m8n8.x4.shared.b16 {%0,%1,%2,%3}, [%4];" \
        : "=r"((r)[0]), "=r"((r)[1]), "=r"((r)[2]), "=r"((r)[3]) : "r"(a))
#define LDSM4T(r, a) \
    asm volatile("ldmatrix.sync.aligned.m8n8.x4.trans.shared.b16 {%0,%1,%2,%3}, [%4];" \
        : "=r"((r)[0]), "=r"((r)[1]), "=r"((r)[2]), "=r"((r)[3]) : "r"(a))

#define MMA_F16(c, a, b0, b1) \
    asm volatile("mma.sync.aligned.m16n8k16.row.col.f32.f16.f16.f32 " \
        "{%0,%1,%2,%3},{%4,%5,%6,%7},{%8,%9},{%0,%1,%2,%3};" \
        : "+f"((c)[0]), "+f"((c)[1]), "+f"((c)[2]), "+f"((c)[3]) \
        : "r"((a)[0]), "r"((a)[1]), "r"((a)[2]), "r"((a)[3]), "r"(b0), "r"(b1))

__device__ __forceinline__ uint2 cvt4(float4 a) {
    __half2 h0 = __floats2half2_rn(a.x, a.y);
    __half2 h1 = __floats2half2_rn(a.z, a.w);
    return make_uint2(*(uint32_t*)&h0, *(uint32_t*)&h1);
}

// ---------------- one-shot converter: x, weights, biases, ss zero ------------
__global__ __launch_bounds__(256) void cvt_all(
    const float4* __restrict__ x,
    const float4* __restrict__ wq, const float4* __restrict__ wk,
    const float4* __restrict__ wv, const float4* __restrict__ wp,
    const float4* __restrict__ wc,
    const float4* __restrict__ bq, const float4* __restrict__ bc,
    const float4* __restrict__ bk, const float4* __restrict__ bv)
{
    constexpr size_t N4X = (size_t)Bb * Nn * Cc / 4;
    constexpr size_t W4  = (size_t)Cc * Cc / 4;
    constexpr size_t WC4 = (size_t)Mm * Cc / 4;
    constexpr size_t O0 = N4X;
    constexpr size_t O1 = O0 + W4;
    constexpr size_t O2 = O1 + W4;
    constexpr size_t O3 = O2 + W4;
    constexpr size_t O4 = O3 + W4;
    constexpr size_t O5 = O4 + WC4;
    constexpr size_t O6 = O5 + WC4;
    constexpr size_t O7 = O6 + 192;
    constexpr size_t O8 = O7 + 16;
    constexpr size_t O9 = O8 + 16;
    constexpr size_t OA = O9 + 192;
    constexpr size_t OB = OA + 192;
    constexpr size_t OC = OB + Bb * Mm / 4;

    size_t i = (size_t)blockIdx.x * 256 + threadIdx.x;
    if (i < O0) {
        ((uint2*)g_xh)[i] = cvt4(x[i]);
    } else if (i < O1) {
        size_t j = i - O0; ((uint2*)g_wqc)[j] = cvt4(wq[j]);
    } else if (i < O2) {
        size_t j = i - O1; ((uint2*)g_wkvp)[j] = cvt4(wk[j]);
    } else if (i < O3) {
        size_t j = i - O2; ((uint2*)(g_wkvp + (size_t)Cc * Cc))[j] = cvt4(wv[j]);
    } else if (i < O4) {
        size_t j = i - O3; ((uint2*)(g_wkvp + (size_t)2 * Cc * Cc))[j] = cvt4(wp[j]);
    } else if (i < O5) {
        size_t j = i - O4; ((uint2*)(g_wqc + (size_t)768 * Cc))[j] = cvt4(wc[j]);
    } else if (i < O6) {
        size_t j = i - O5; ((uint2*)(g_wqc + (size_t)832 * Cc))[j] = make_uint2(0, 0);
    } else if (i < O7) {
        size_t j = i - O6; ((float4*)g_bqc)[j] = bq[j];
    } else if (i < O8) {
        size_t j = i - O7; ((float4*)(g_bqc + 768))[j] = bc[j];
    } else if (i < O9) {
        size_t j = i - O8;
        ((float4*)(g_bqc + 832))[j] = make_float4(0.f, 0.f, 0.f, 0.f);
    } else if (i < OA) {
        size_t j = i - O9; ((float4*)g_bkv)[j] = bk[j];
    } else if (i < OB) {
        size_t j = i - OA; ((float4*)(g_bkv + Cc))[j] = bv[j];
    } else if (i < OC) {
        size_t j = i - OB;
        ((float4*)g_ss)[j] = make_float4(0.f, 0.f, 0.f, 0.f);
    }
}

// ---------------- fp16 GEMM NT via mma.sync (2-stage pipeline) ---------------
// C(I,J) = A(I,768)·B(J,768)^T + bias.
// MODE 0: plain. MODE 2: fused Q+cluster epilogue. MODE 3: per-A-row L2 scale.
template <int TN, int MODE, bool OUTH>
__global__ __launch_bounds__(256) void gemm_tc(
    const __half* __restrict__ Ah, const __half* __restrict__ Bh,
    const float* __restrict__ rss,
    const float* __restrict__ bias, void* __restrict__ CoutV, int J)
{
    constexpr int K = Cc;
    constexpr int KC = 32;
    constexpr int NCH = K / KC;        // 24
    constexpr int ABY = 128 * 64;      // 8 KB
    constexpr int BBY = TN * 64;
    constexpr int STAGE = ABY + BBY;
    constexpr int TNW = TN / 4;
    constexpr int NT = TNW / 8;
    constexpr int NP = NT / 2;

    extern __shared__ char smem[];
    const uint32_t s0 = smem_u32(smem);
    const uint32_t sb[2] = {s0, s0 + STAGE};

    const int tid = threadIdx.x;
    const int wid = tid >> 5;
    const int lane = tid & 31;
    const int wm = wid & 1;
    const int wn = wid >> 1;
    const int i0 = blockIdx.y * 128;
    const int j0 = blockIdx.x * TN;

    float acc[4][NT][4];
#pragma unroll
    for (int a = 0; a < 4; a++)
#pragma unroll
        for (int b = 0; b < NT; b++)
#pragma unroll
            for (int c = 0; c < 4; c++) acc[a][b][c] = 0.f;

    auto prefetch = [&](int ch, int s) {
        const uint32_t base = sb[s];
        const int k0 = ch * KC;
#pragma unroll
        for (int it = 0; it < 2; it++) {
            int id = tid + it * 256;
            int row = id >> 2, c = id & 3;
            uint32_t off = row * 64 + (((c ^ (row >> 1)) & 3) << 4);
            CP16(base + off, Ah + (size_t)(i0 + row) * K + k0 + c * 8);
        }
#pragma unroll
        for (int it = 0; it < (TN * 4) / 256; it++) {
            int id = tid + it * 256;
            int row = id >> 2, c = id & 3;
            uint32_t off = row * 64 + (((c ^ (row >> 1)) & 3) << 4);
            CP16(base + ABY + off, Bh + (size_t)(j0 + row) * K + k0 + c * 8);
        }
    };

    auto compute = [&](int s) {
        const uint32_t ab = sb[s];
        const uint32_t bhb = ab + ABY;
#pragma unroll
        for (int ks = 0; ks < 2; ks++) {
            uint32_t BH[NP][4];
#pragma unroll
            for (int p = 0; p < NP; p++) {
                int row = wn * TNW + p * 16 + (lane & 15);
                int ch = ks * 2 + (lane >> 4);
                uint32_t off = row * 64 + (((ch ^ (row >> 1)) & 3) << 4);
                LDSM4(BH[p], bhb + off);
            }
#pragma unroll
            for (int mt = 0; mt < 4; mt++) {
                int row = wm * 64 + mt * 16 + (lane & 15);
                int ch = ks * 2 + (lane >> 4);
                uint32_t off = row * 64 + (((ch ^ (row >> 1)) & 3) << 4);
                uint32_t AH[4];
                LDSM4(AH, ab + off);
#pragma unroll
                for (int nt = 0; nt < NT; nt++)
                    MMA_F16(acc[mt][nt], AH,
                            BH[nt >> 1][nt & 1], BH[nt >> 1][(nt & 1) + 2]);
            }
        }
    };

    prefetch(0, 0);
    CP_COMMIT();
    for (int ch = 0; ch < NCH; ch++) {
        if (ch + 1 < NCH) {
            prefetch(ch + 1, (ch + 1) & 1);
            CP_COMMIT();
            CP_WAIT(1);
        } else {
            CP_WAIT(0);
        }
        __syncthreads();
        compute(ch & 1);
        __syncthreads();
    }

#pragma unroll
    for (int mt = 0; mt < 4; mt++) {
        const int gr = i0 + wm * 64 + mt * 16 + (lane >> 2);
        float inv0 = 1.f, inv1 = 1.f;
        if constexpr (MODE == 3) {
            inv0 = 1.f / fmaxf(sqrtf(__ldg(rss + gr)), 1e-12f);
            inv1 = 1.f / fmaxf(sqrtf(__ldg(rss + gr + 8)), 1e-12f);
        }
#pragma unroll
        for (int nt = 0; nt < NT; nt++) {
            const int gc = j0 + wn * TNW + nt * 8 + (lane & 3) * 2;
            const float b0 = __ldg(bias + gc), b1 = __ldg(bias + gc + 1);
            float v0, v1, v2, v3;
            if constexpr (MODE == 3) {
                v0 = acc[mt][nt][0] * inv0 + b0;
                v1 = acc[mt][nt][1] * inv0 + b1;
                v2 = acc[mt][nt][2] * inv1 + b0;
                v3 = acc[mt][nt][3] * inv1 + b1;
            } else {
                v0 = acc[mt][nt][0] + b0; v1 = acc[mt][nt][1] + b1;
                v2 = acc[mt][nt][2] + b0; v3 = acc[mt][nt][3] + b1;
            }
            if constexpr (MODE == 2) {
                if (gc < Cc) {
                    __half2 h0 = __floats2half2_rn(v0, v1);
                    __half2 h1 = __floats2half2_rn(v2, v3);
                    *(__half2*)(g_qh + (size_t)gr * Cc + gc) = h0;
                    *(__half2*)(g_qh + (size_t)(gr + 8) * Cc + gc) = h1;
                } else {
                    const int gcl = gc - Cc;
                    if (gcl < Mm) {
                        v0 = 1.f / (1.f + __expf(-v0)) * (1.f / Nn);
                        v1 = 1.f / (1.f + __expf(-v1)) * (1.f / Nn);
                        v2 = 1.f / (1.f + __expf(-v2)) * (1.f / Nn);
                        v3 = 1.f / (1.f + __expf(-v3)) * (1.f / Nn);
                        __half2 h0 = __floats2half2_rn(v0, v1);
                        __half2 h1 = __floats2half2_rn(v2, v3);
                        *(__half2*)(g_cth + (size_t)gr * Mm + gcl) = h0;
                        *(__half2*)(g_cth + (size_t)(gr + 8) * Mm + gcl) = h1;
                    }
                }
            } else if constexpr (OUTH) {
                __half* Ch = (__half*)CoutV;
                __half2 h0 = __floats2half2_rn(v0, v1);
                __half2 h1 = __floats2half2_rn(v2, v3);
                *(__half2*)(Ch + (size_t)gr * J + gc) = h0;
                *(__half2*)(Ch + (size_t)(gr + 8) * J + gc) = h1;
            } else {
                float* Cf = (float*)CoutV;
                *(float2*)(Cf + (size_t)gr * J + gc) = make_float2(v0, v1);
                *(float2*)(Cf + (size_t)(gr + 8) * J + gc) = make_float2(v2, v3);
            }
        }
    }
}

// ---------------- tensor-core z = ct^T @ x: fp16 z + row sumsq atomics -------
__global__ __launch_bounds__(256) void gemm_ctz(
    const __half* __restrict__ ct, const __half* __restrict__ xh,
    __half* __restrict__ zh, float* __restrict__ ss)
{
    constexpr int KC = 32;
    constexpr int NCH = Nn / KC;     // 32
    constexpr int CTBY = 32 * 128;   // 4 KB
    constexpr int XBY  = 32 * 256;   // 8 KB
    constexpr int STAGE = CTBY + XBY;

    __shared__ __align__(128) char smem[2 * STAGE];   // 24 KB
    const uint32_t s0 = smem_u32(smem);

    const int b = blockIdx.z;
    const int j0 = blockIdx.x * 128;
    const int tid = threadIdx.x;
    const int wid = tid >> 5, lane = tid & 31;
    const int m0 = (wid & 3) * 16;
    const int jw = (wid >> 2) * 64;

    float o[8][4];
#pragma unroll
    for (int t = 0; t < 8; t++)
#pragma unroll
        for (int c = 0; c < 4; c++) o[t][c] = 0.f;

    auto prefetch = [&](int chn, int s) {
        const uint32_t base = s0 + s * STAGE;
        const int k0 = chn * KC;
        {
            int r = tid >> 3, c = tid & 7;
            uint32_t off = r * 128 + (((c ^ (r & 7)) & 7) << 4);
            CP16(base + off, ct + ((size_t)b * Nn + k0 + r) * Mm + c * 8);
        }
#pragma unroll
        for (int it = 0; it < 2; it++) {
            int id = tid + it * 256;
            int r = id >> 4, c = id & 15;
            uint32_t off = r * 256 + (((c ^ (r & 7)) & 15) << 4);
            CP16(base + CTBY + off,
                 xh + ((size_t)b * Nn + k0 + r) * Cc + j0 + c * 8);
        }
    };

    auto compute = [&](int s) {
        const uint32_t cb = s0 + s * STAGE, xb = cb + CTBY;
#pragma unroll
        for (int ks = 0; ks < 2; ks++) {
            const int row = ks * 16 + (lane & 7) + ((lane >> 4) & 1) * 8;
            uint32_t A[4];
            {
                int c = (m0 >> 3) + ((lane >> 3) & 1);
                LDSM4T(A, cb + row * 128 + (((c ^ (row & 7)) & 7) << 4));
            }
#pragma unroll
            for (int jt = 0; jt < 4; jt++) {
                uint32_t Bf[4];
                int c = ((jw + jt * 16) >> 3) + ((lane >> 3) & 1);
                LDSM4T(Bf, xb + row * 256 + (((c ^ (row & 7)) & 15) << 4));
                MMA_F16(o[jt * 2],     A, Bf[0], Bf[2]);
                MMA_F16(o[jt * 2 + 1], A, Bf[1], Bf[3]);
            }
        }
    };

    prefetch(0, 0);
    CP_COMMIT();
    for (int ch = 0; ch < NCH; ch++) {
        if (ch + 1 < NCH) {
            prefetch(ch + 1, (ch + 1) & 1);
            CP_COMMIT();
            CP_WAIT(1);
        } else {
            CP_WAIT(0);
        }
        __syncthreads();
        compute(ch & 1);
        __syncthreads();
    }

    const int r0 = m0 + (lane >> 2);
    float s0acc = 0.f, s1acc = 0.f;
#pragma unroll
    for (int t = 0; t < 8; t++) {
        const int col = j0 + jw + t * 8 + (lane & 3) * 2;
        __half* zp = zh + ((size_t)b * Mm + r0) * Cc + col;
        __half2 h0 = __floats2half2_rn(o[t][0], o[t][1]);
        __half2 h1 = __floats2half2_rn(o[t][2], o[t][3]);
        *(__half2*)zp = h0;
        *(__half2*)(zp + 8 * Cc) = h1;
        s0acc += o[t][0] * o[t][0] + o[t][1] * o[t][1];
        s1acc += o[t][2] * o[t][2] + o[t][3] * o[t][3];
    }
    atomicAdd(ss + b * Mm + r0, s0acc);
    atomicAdd(ss + b * Mm + r0 + 8, s1acc);
}

// ---------------- tensor-core attention --------------------------------------
__global__ __launch_bounds__(256) void attn_tc(
    const __half* __restrict__ qh, const __half* __restrict__ kvh,
    __half* __restrict__ oh)
{
    const int bh = blockIdx.x;
    const int b = bh / Hh;
    const int h = bh % Hh;
    const int n0 = blockIdx.y * 128;

    __shared__ __align__(128) char smem[32768];
    const uint32_t sq = smem_u32(smem);
    const uint32_t sk = sq + 16384;
    const uint32_t sv = sk + 8192;

    const int tid = threadIdx.x;
    const int wid = tid >> 5;
    const int lane = tid & 31;

#pragma unroll
    for (int it = 0; it < 4; it++) {
        int id = tid + it * 256;
        int row = id >> 3, c = id & 7;
        uint32_t off = row * 128 + (((c ^ row) & 7) << 4);
        CP16(sq + off, qh + (size_t)(b * Nn + n0 + row) * Cc + h * Dd + c * 8);
    }
#pragma unroll
    for (int it = 0; it < 2; it++) {
        int id = tid + it * 256;
        int row = id >> 3, c = id & 7;
        uint32_t off = row * 128 + (((c ^ row) & 7) << 4);
        const size_t base = (size_t)(b * Mm + row) * (2 * Cc) + h * Dd + c * 8;
        CP16(sk + off, kvh + base);
        CP16(sv + off, kvh + base + Cc);
    }
    CP_COMMIT();
    CP_WAIT(0);
    __syncthreads();

    float s[8][4];
#pragma unroll
    for (int t = 0; t < 8; t++)
#pragma unroll
        for (int c = 0; c < 4; c++) s[t][c] = 0.f;

#pragma unroll
    for (int kf = 0; kf < 4; kf++) {
        const int ch = kf * 2 + (lane >> 4);
        uint32_t A[4];
        {
            int row = wid * 16 + (lane & 15);
            LDSM4(A, sq + row * 128 + (((ch ^ row) & 7) << 4));
        }
        uint32_t Bk[4][4];
#pragma unroll
        for (int p = 0; p < 4; p++) {
            int row = p * 16 + (lane & 15);
            LDSM4(Bk[p], sk + row * 128 + (((ch ^ row) & 7) << 4));
        }
#pragma unroll
        for (int nt = 0; nt < 8; nt++)
            MMA_F16(s[nt], A, Bk[nt >> 1][nt & 1], Bk[nt >> 1][(nt & 1) + 2]);
    }

    const float scale = 0.125f;
    float m0 = -1e30f, m1 = -1e30f;
#pragma unroll
    for (int t = 0; t < 8; t++) {
#pragma unroll
        for (int c = 0; c < 4; c++) s[t][c] *= scale;
        m0 = fmaxf(m0, fmaxf(s[t][0], s[t][1]));
        m1 = fmaxf(m1, fmaxf(s[t][2], s[t][3]));
    }
    m0 = fmaxf(m0, __shfl_xor_sync(0xffffffff, m0, 1));
    m0 = fmaxf(m0, __shfl_xor_sync(0xffffffff, m0, 2));
    m1 = fmaxf(m1, __shfl_xor_sync(0xffffffff, m1, 1));
    m1 = fmaxf(m1, __shfl_xor_sync(0xffffffff, m1, 2));

    float l0 = 0.f, l1 = 0.f;
    uint32_t P[4][4];
#pragma unroll
    for (int t = 0; t < 8; t++) {
        float p0 = __expf(s[t][0] - m0);
        float p1 = __expf(s[t][1] - m0);
        float p2 = __expf(s[t][2] - m1);
        float p3 = __expf(s[t][3] - m1);
        l0 += p0 + p1;
        l1 += p2 + p3;
        __half2 h01 = __floats2half2_rn(p0, p1);
        __half2 h23 = __floats2half2_rn(p2, p3);
        P[t >> 1][(t & 1) * 2 + 0] = *(uint32_t*)&h01;
        P[t >> 1][(t & 1) * 2 + 1] = *(uint32_t*)&h23;
    }
    l0 += __shfl_xor_sync(0xffffffff, l0, 1);
    l0 += __shfl_xor_sync(0xffffffff, l0, 2);
    l1 += __shfl_xor_sync(0xffffffff, l1, 1);
    l1 += __shfl_xor_sync(0xffffffff, l1, 2);

    float o[8][4];
#pragma unroll
    for (int t = 0; t < 8; t++)
#pragma unroll
        for (int c = 0; c < 4; c++) o[t][c] = 0.f;

#pragma unroll
    for (int kf = 0; kf < 4; kf++) {
#pragma unroll
        for (int dt = 0; dt < 4; dt++) {
            uint32_t VF[4];
            int row = kf * 16 + (lane & 15);
            int ch = dt * 2 + (lane >> 4);
            LDSM4T(VF, sv + row * 128 + (((ch ^ row) & 7) << 4));
            MMA_F16(o[dt * 2],     P[kf], VF[0], VF[1]);
            MMA_F16(o[dt * 2 + 1], P[kf], VF[2], VF[3]);
        }
    }

    const float inv0 = 1.f / l0, inv1 = 1.f / l1;
    const int r = wid * 16 + (lane >> 2);
    const size_t ob = (size_t)(b * Nn + n0 + r) * Cc + h * Dd;
#pragma unroll
    for (int t = 0; t < 8; t++) {
        const int col = t * 8 + (lane & 3) * 2;
        __half2 h0 = __floats2half2_rn(o[t][0] * inv0, o[t][1] * inv0);
        __half2 h1 = __floats2half2_rn(o[t][2] * inv1, o[t][3] * inv1);
        *(__half2*)(oh + ob + col) = h0;
        *(__half2*)(oh + ob + 8 * Cc + col) = h1;
    }
}

// ---------------------------------------------------------------------------
extern "C" void kernel_launch(void* const* d_in, const int* in_sizes, int n_in,
                              void* d_out, int out_size)
{
    (void)in_sizes; (void)n_in; (void)out_size;
    const float* x  = (const float*)d_in[0];
    const float* Wc = (const float*)d_in[1];
    const float* bc = (const float*)d_in[2];
    const float* Wq = (const float*)d_in[3];
    const float* bq = (const float*)d_in[4];
    const float* Wk = (const float*)d_in[5];
    const float* bk = (const float*)d_in[6];
    const float* Wv = (const float*)d_in[7];
    const float* bv = (const float*)d_in[8];
    const float* Wp = (const float*)d_in[9];
    const float* bp = (const float*)d_in[10];
    float* out = (float*)d_out;

    float *ss, *bkv, *bqc;
    __half *cth, *xh, *qh, *kvh, *oh, *zh, *wqc, *wkvp;
    cudaGetSymbolAddress((void**)&ss,   g_ss);
    cudaGetSymbolAddress((void**)&bkv,  g_bkv);
    cudaGetSymbolAddress((void**)&bqc,  g_bqc);
    cudaGetSymbolAddress((void**)&cth,  g_cth);
    cudaGetSymbolAddress((void**)&xh,   g_xh);
    cudaGetSymbolAddress((void**)&qh,   g_qh);
    cudaGetSymbolAddress((void**)&kvh,  g_kvh);
    cudaGetSymbolAddress((void**)&oh,   g_oh);
    cudaGetSymbolAddress((void**)&zh,   g_zh);
    cudaGetSymbolAddress((void**)&wqc,  g_wqc);
    cudaGetSymbolAddress((void**)&wkvp, g_wkvp);

    constexpr int SMEM2 = 2 * (128 * 64 + 128 * 64);   // 32 KB (2-stage)
    cudaFuncSetAttribute(gemm_tc<128, 0, false>,
        cudaFuncAttributeMaxDynamicSharedMemorySize, SMEM2);
    cudaFuncSetAttribute(gemm_tc<128, 0, true>,
        cudaFuncAttributeMaxDynamicSharedMemorySize, SMEM2);
    cudaFuncSetAttribute(gemm_tc<128, 2, true>,
        cudaFuncAttributeMaxDynamicSharedMemorySize, SMEM2);
    cudaFuncSetAttribute(gemm_tc<128, 3, true>,
        cudaFuncAttributeMaxDynamicSharedMemorySize, SMEM2);

    const int IN = Bb * Nn;   // 32768
    const int IM = Bb * Mm;   // 2048

    // 1. one-shot convert (x, weights, biases) + g_ss zeroing
    {
        constexpr size_t TOT = (size_t)Bb * Nn * Cc / 4 + 4 * (Cc * Cc / 4)
                             + 2 * (Mm * Cc / 4) + 192 + 16 + 16 + 192 + 192
                             + Bb * Mm / 4;
        cvt_all<<<(unsigned)((TOT + 255) / 256), 256>>>(
            (const float4*)x, (const float4*)Wq, (const float4*)Wk,
            (const float4*)Wv, (const float4*)Wp, (const float4*)Wc,
            (const float4*)bq, (const float4*)bc,
            (const float4*)bk, (const float4*)bv);
    }

    // 2. fused Q + cluster logits: [q | ct] = x @ [Wq|Wc|0]^T + [bq|bc|0]
    gemm_tc<128, 2, true><<<dim3(7, IN / 128), 256, SMEM2>>>(
        xh, wqc, nullptr, bqc, nullptr, 896);

    // 3. z[b] = ct[b]^T @ x[b] -> fp16 zh + per-row sumsq atomics
    gemm_ctz<<<dim3(Cc / 128, 1, Bb), 256>>>(cth, xh, zh, ss);

    // 4. KV = norm(z) @ [Wk|Wv]^T + [bk|bv] -> fp16 (L2 scale in epilogue)
    gemm_tc<128, 3, true><<<dim3(2 * Cc / 128, IM / 128), 256, SMEM2>>>(
        zh, wkvp, ss, bkv, kvh, 2 * Cc);

    // 5. tensor-core attention -> o (fp16)
    attn_tc<<<dim3(Bb * Hh, Nn / 128), 256>>>(qh, kvh, oh);

    // 6. out = o @ Wp^T + bp (fp32 out)
    gemm_tc<128, 0, false><<<dim3(Cc / 128, IN / 128), 256, SMEM2>>>(
        oh, wkvp + (size_t)2 * Cc * Cc, nullptr, bp, out, Cc);
}